// round 4
// baseline (speedup 1.0000x reference)
#include <cuda_runtime.h>
#include <stdint.h>

// Problem constants
#define D      256
#define KCODES 4096
#define NROWS  16384

#define THREADS 512
#define BM 128
#define BN 256
#define BK 32
#define KV 768                    // virtual contraction: 3 tf32-split terms x 256
#define STAGES_PER_TILE (KV / BK) // 24
#define NT (KCODES / BN)          // 16
#define TOTAL_STAGES (STAGES_PER_TILE * NT)  // 384

// smem stage geometry (floats): rows padded 32 -> 36 words (144B, 16B aligned)
#define ROWPAD 36
#define A_STAGE_BYTES (BM * ROWPAD * 4)   // 18432
#define B_STAGE_BYTES (BN * ROWPAD * 4)   // 36864
#define STAGE_BYTES   (A_STAGE_BYTES + B_STAGE_BYTES)
#define SMEM_TOTAL    (2 * STAGE_BYTES)   // 110592

#define EMA_DECAY 0.99f
#define ONE_MINUS_DECAY 0.01f
#define EPS 1e-5f

// ---------------- device scratch ----------------
__device__ float g_cnorm[KCODES];
__device__ float g_n[KCODES];
__device__ int   g_idx[NROWS];
__device__ float g_scal[2];
__device__ float g_za[(size_t)NROWS * KV];    // [zhi | zhi | zlo], k-permuted per 32-block
__device__ float g_cbp[(size_t)KCODES * KV];  // [chi | clo | chi], k-permuted per 32-block

// ---------------- helpers ----------------
__device__ __forceinline__ uint32_t smem_u32(const void* p) {
    uint32_t a;
    asm("{ .reg .u64 t; cvta.to.shared.u64 t, %1; cvt.u32.u64 %0, t; }" : "=r"(a) : "l"(p));
    return a;
}
__device__ __forceinline__ void cpasync16(uint32_t dst, const float* src) {
    asm volatile("cp.async.cg.shared.global [%0], [%1], 16;" :: "r"(dst), "l"(src));
}
__device__ __forceinline__ void cp_commit() {
    asm volatile("cp.async.commit_group;" ::: "memory");
}
__device__ __forceinline__ void cp_wait1() {
    asm volatile("cp.async.wait_group 1;" ::: "memory");
}
__device__ __forceinline__ void cp_wait0() {
    asm volatile("cp.async.wait_group 0;" ::: "memory");
}
__device__ __forceinline__ void mma_tf32(float* c, uint32_t a0, uint32_t a1,
                                         uint32_t a2, uint32_t a3,
                                         uint32_t b0, uint32_t b1) {
    asm volatile(
        "mma.sync.aligned.m16n8k8.row.col.f32.tf32.tf32.f32 "
        "{%0,%1,%2,%3}, {%4,%5,%6,%7}, {%8,%9}, {%0,%1,%2,%3};"
        : "+f"(c[0]), "+f"(c[1]), "+f"(c[2]), "+f"(c[3])
        : "r"(a0), "r"(a1), "r"(a2), "r"(a3), "r"(b0), "r"(b1));
}
__device__ __forceinline__ float tf32_rna(float v) {
    uint32_t u;
    asm("cvt.rna.tf32.f32 %0, %1;" : "=r"(u) : "f"(v));
    return __uint_as_float(u);
}
__device__ __forceinline__ uint32_t fbits(float v) { return __float_as_uint(v); }

// ---------------- kernel 0: init ----------------
__global__ __launch_bounds__(256) void vq_init_kernel(
    const float* __restrict__ ema_weight, float* __restrict__ out_weight)
{
    int i = blockIdx.x * 256 + threadIdx.x;
    out_weight[i] = EMA_DECAY * ema_weight[i];
    if (i < KCODES) g_n[i] = 0.0f;
    if (i < 2) g_scal[i] = 0.0f;
}

// ---------------- kernel 1: codebook half-norms ----------------
__global__ __launch_bounds__(256) void vq_cnorm_kernel(const float* __restrict__ cb)
{
    int k = blockIdx.x;
    float v = cb[(size_t)k * D + threadIdx.x];
    float s = v * v;
    #pragma unroll
    for (int off = 16; off > 0; off >>= 1)
        s += __shfl_down_sync(0xffffffffu, s, off);
    __shared__ float ws[8];
    int lane = threadIdx.x & 31, wid = threadIdx.x >> 5;
    if (lane == 0) ws[wid] = s;
    __syncthreads();
    if (threadIdx.x == 0) {
        float t = 0.f;
        #pragma unroll
        for (int w = 0; w < 8; ++w) t += ws[w];
        g_cnorm[k] = 0.5f * t;
    }
}

// ---------------- kernel 2: split + pack (virtual K=768, k-permuted) ----------------
// perm within each 32-block: slot p holds local k = (p>>3) + 4*(p&7)
__global__ __launch_bounds__(256) void vq_pack_kernel(const float* __restrict__ src, int isB)
{
    int o = blockIdx.x * 256 + threadIdx.x;          // linear into [rows][768]
    int row = o / KV;
    int v   = o - row * KV;
    int blk = v >> 5;
    int p   = v & 31;
    int kl  = (p >> 3) + ((p & 7) << 2);
    int vc  = blk * 32 + kl;                         // virtual column
    int term = vc >> 8;
    int d    = vc & 255;
    float x  = src[(size_t)row * D + d];
    float hi = tf32_rna(x);
    float val;
    if (isB) val = (term == 1) ? tf32_rna(x - hi) : hi;   // [chi | clo | chi]
    else     val = (term == 2) ? tf32_rna(x - hi) : hi;   // [zhi | zhi | zlo]
    if (isB) g_cbp[o] = val;
    else     g_za[o]  = val;
}

// ---------------- kernel 3: warp-mma tf32 GEMM + fused argmax ----------------
__global__ __launch_bounds__(THREADS, 1) void vq_mma_kernel()
{
    extern __shared__ char smem[];
    const uint32_t sbase = smem_u32(smem);
    const int tid  = threadIdx.x;
    const int wid  = tid >> 5;
    const int lane = tid & 31;
    const int r    = lane >> 2;        // 0..7
    const int q    = lane & 3;         // 0..3
    const int wm   = (wid >> 2) * 32;  // warp row base (4 warp-rows)
    const int wn   = (wid & 3) * 64;   // warp col base (4 warp-cols)
    const int mBase = blockIdx.x * BM;

    // per-thread smem byte offsets for fragment loads (h adds +16)
    uint32_t aoff[2][2];
    #pragma unroll
    for (int mf = 0; mf < 2; ++mf)
        #pragma unroll
        for (int rr = 0; rr < 2; ++rr)
            aoff[mf][rr] = (uint32_t)(wm + mf * 16 + rr * 8 + r) * 144u + (uint32_t)q * 32u;
    uint32_t boff[8];
    #pragma unroll
    for (int nf = 0; nf < 8; ++nf)
        boff[nf] = (uint32_t)(wn + nf * 8 + r) * 144u + (uint32_t)q * 32u;

    float acc[2][8][4];
    float bestS[2][2];
    int   bestI[2][2];
    #pragma unroll
    for (int mf = 0; mf < 2; ++mf)
        #pragma unroll
        for (int rr = 0; rr < 2; ++rr) { bestS[mf][rr] = -3.402823e38f; bestI[mf][rr] = 0x7fffffff; }

    // ---- cp.async stage issue ----
    auto issue = [&](int s, int buf) {
        int nt = s / STAGES_PER_TILE;
        int ks = s - nt * STAGES_PER_TILE;
        int koff = ks * BK;
        uint32_t abase = sbase + (uint32_t)buf * STAGE_BYTES;
        uint32_t bbase = abase + A_STAGE_BYTES;
        const float* Asrc = g_za + (size_t)mBase * KV + koff;
        const float* Bsrc = g_cbp + (size_t)(nt * BN) * KV + koff;
        #pragma unroll
        for (int t = 0; t < 2; ++t) {
            int i = tid + t * THREADS;            // 0..1023
            int row = i >> 3, c = i & 7;
            cpasync16(abase + (uint32_t)row * 144u + (uint32_t)c * 16u,
                      Asrc + (size_t)row * KV + c * 4);
        }
        #pragma unroll
        for (int t = 0; t < 4; ++t) {
            int i = tid + t * THREADS;            // 0..2047
            int row = i >> 3, c = i & 7;
            cpasync16(bbase + (uint32_t)row * 144u + (uint32_t)c * 16u,
                      Bsrc + (size_t)row * KV + c * 4);
        }
        cp_commit();
    };

    issue(0, 0);

    for (int s = 0; s < TOTAL_STAGES; ++s) {
        const int buf = s & 1;
        if (s < TOTAL_STAGES - 1) { issue(s + 1, buf ^ 1); cp_wait1(); }
        else                       { cp_wait0(); }
        __syncthreads();

        int nt = s / STAGES_PER_TILE;
        int ks = s - nt * STAGES_PER_TILE;
        if (ks == 0) {
            #pragma unroll
            for (int mf = 0; mf < 2; ++mf)
                #pragma unroll
                for (int nf = 0; nf < 8; ++nf)
                    #pragma unroll
                    for (int e = 0; e < 4; ++e) acc[mf][nf][e] = 0.0f;
        }

        uint32_t abase = sbase + (uint32_t)buf * STAGE_BYTES;
        uint32_t bbase = abase + A_STAGE_BYTES;

        #pragma unroll
        for (int h = 0; h < 2; ++h) {
            float4 Af[2][2];
            #pragma unroll
            for (int mf = 0; mf < 2; ++mf)
                #pragma unroll
                for (int rr = 0; rr < 2; ++rr) {
                    uint32_t addr = abase + aoff[mf][rr] + (uint32_t)h * 16u;
                    asm volatile("ld.shared.v4.f32 {%0,%1,%2,%3}, [%4];"
                        : "=f"(Af[mf][rr].x), "=f"(Af[mf][rr].y),
                          "=f"(Af[mf][rr].z), "=f"(Af[mf][rr].w)
                        : "r"(addr));
                }
            #pragma unroll
            for (int nf = 0; nf < 8; ++nf) {
                float4 Bf;
                uint32_t addr = bbase + boff[nf] + (uint32_t)h * 16u;
                asm volatile("ld.shared.v4.f32 {%0,%1,%2,%3}, [%4];"
                    : "=f"(Bf.x), "=f"(Bf.y), "=f"(Bf.z), "=f"(Bf.w)
                    : "r"(addr));
                #pragma unroll
                for (int mf = 0; mf < 2; ++mf) {
                    // k8 step 0 of this half
                    mma_tf32(acc[mf][nf],
                             fbits(Af[mf][0].x), fbits(Af[mf][1].x),
                             fbits(Af[mf][0].y), fbits(Af[mf][1].y),
                             fbits(Bf.x), fbits(Bf.y));
                    // k8 step 1 of this half
                    mma_tf32(acc[mf][nf],
                             fbits(Af[mf][0].z), fbits(Af[mf][1].z),
                             fbits(Af[mf][0].w), fbits(Af[mf][1].w),
                             fbits(Bf.z), fbits(Bf.w));
                }
            }
        }

        if (ks == STAGES_PER_TILE - 1) {
            // fold -0.5*||c||^2 and update running argmax
            int ntBase = nt * BN;
            #pragma unroll
            for (int nf = 0; nf < 8; ++nf) {
                int colb = ntBase + wn + nf * 8 + q * 2;
                float cn0 = __ldg(&g_cnorm[colb]);
                float cn1 = __ldg(&g_cnorm[colb + 1]);
                #pragma unroll
                for (int mf = 0; mf < 2; ++mf) {
                    float s0 = acc[mf][nf][0] - cn0;
                    float s1 = acc[mf][nf][1] - cn1;
                    float s2 = acc[mf][nf][2] - cn0;
                    float s3 = acc[mf][nf][3] - cn1;
                    if (s0 > bestS[mf][0]) { bestS[mf][0] = s0; bestI[mf][0] = colb; }
                    if (s1 > bestS[mf][0]) { bestS[mf][0] = s1; bestI[mf][0] = colb + 1; }
                    if (s2 > bestS[mf][1]) { bestS[mf][1] = s2; bestI[mf][1] = colb; }
                    if (s3 > bestS[mf][1]) { bestS[mf][1] = s3; bestI[mf][1] = colb + 1; }
                }
            }
        }
        __syncthreads();
    }

    // ---- final cross-thread reduction (16 candidates per row) ----
    float* redS = reinterpret_cast<float*>(smem);
    int*   redI = reinterpret_cast<int*>(smem + BM * 16 * 4);
    int c16 = (wid & 3) * 4 + q;
    #pragma unroll
    for (int mf = 0; mf < 2; ++mf)
        #pragma unroll
        for (int rr = 0; rr < 2; ++rr) {
            int row = wm + mf * 16 + rr * 8 + r;
            redS[row * 16 + c16] = bestS[mf][rr];
            redI[row * 16 + c16] = bestI[mf][rr];
        }
    __syncthreads();
    if (tid < BM) {
        float bs = redS[tid * 16];
        int   bi = redI[tid * 16];
        #pragma unroll
        for (int j = 1; j < 16; ++j) {
            float sv = redS[tid * 16 + j];
            int   iv = redI[tid * 16 + j];
            if (sv > bs || (sv == bs && iv < bi)) { bs = sv; bi = iv; }
        }
        g_idx[mBase + tid] = bi;
    }
}

// ---------------- kernel 4: gather + loss + EMA scatter ----------------
__global__ __launch_bounds__(256) void vq_gather_kernel(
    const float* __restrict__ z, const float* __restrict__ cb,
    const float* __restrict__ mask,
    float* __restrict__ out_q, float* __restrict__ out_idx,
    float* __restrict__ out_weight)
{
    int tid = threadIdx.x;
    int l   = tid & 63;
    int row = blockIdx.x * 4 + (tid >> 6);
    int idx = g_idx[row];
    float m = mask[row];

    float4 zv = reinterpret_cast<const float4*>(z  + (size_t)row * D)[l];
    float4 qv = reinterpret_cast<const float4*>(cb + (size_t)idx * D)[l];
    float4 o;
    o.x = zv.x + (qv.x - zv.x); o.y = zv.y + (qv.y - zv.y);
    o.z = zv.z + (qv.z - zv.z); o.w = zv.w + (qv.w - zv.w);
    reinterpret_cast<float4*>(out_q + (size_t)row * D)[l] = o;

    if (m != 0.0f) {
        float* w = out_weight + (size_t)idx * D + l * 4;
        atomicAdd(w + 0, ONE_MINUS_DECAY * m * zv.x);
        atomicAdd(w + 1, ONE_MINUS_DECAY * m * zv.y);
        atomicAdd(w + 2, ONE_MINUS_DECAY * m * zv.z);
        atomicAdd(w + 3, ONE_MINUS_DECAY * m * zv.w);
    }

    float dx = zv.x - qv.x, dy = zv.y - qv.y, dz = zv.z - qv.z, dw = zv.w - qv.w;
    float s = m * (dx * dx + dy * dy + dz * dz + dw * dw);
    #pragma unroll
    for (int off = 16; off > 0; off >>= 1)
        s += __shfl_down_sync(0xffffffffu, s, off);
    __shared__ float ws[8];
    int lane = tid & 31, wd = tid >> 5;
    if (lane == 0) ws[wd] = s;
    __syncthreads();
    if (tid == 0) {
        float t = 0.f;
        #pragma unroll
        for (int w = 0; w < 8; ++w) t += ws[w];
        atomicAdd(&g_scal[0], t * (1.0f / (float)D));
    }
    if (l == 0) {
        out_idx[row] = (float)idx;
        atomicAdd(&g_scal[1], m);
        atomicAdd(&g_n[idx], m);
    }
}

// ---------------- kernel 5: finalize ----------------
__global__ __launch_bounds__(1024) void vq_finalize_kernel(
    const float* __restrict__ ema_count,
    float* __restrict__ out_count, float* __restrict__ out_loss)
{
    __shared__ float cbuf[KCODES];
    __shared__ float red[32];
    __shared__ float s_total;
    int tid = threadIdx.x;

    float local = 0.0f;
    for (int k = tid; k < KCODES; k += 1024) {
        float c = EMA_DECAY * ema_count[k] + ONE_MINUS_DECAY * g_n[k];
        cbuf[k] = c;
        local += c;
    }
    #pragma unroll
    for (int off = 16; off > 0; off >>= 1)
        local += __shfl_down_sync(0xffffffffu, local, off);
    int lane = tid & 31, wid = tid >> 5;
    if (lane == 0) red[wid] = local;
    __syncthreads();
    if (wid == 0) {
        float v = red[lane];
        #pragma unroll
        for (int off = 16; off > 0; off >>= 1)
            v += __shfl_down_sync(0xffffffffu, v, off);
        if (lane == 0) s_total = v;
    }
    __syncthreads();
    float total = s_total;
    float inv = total / (total + (float)KCODES * EPS);
    for (int k = tid; k < KCODES; k += 1024)
        out_count[k] = (cbuf[k] + EPS) * inv;

    if (tid == 0)
        out_loss[0] = 10.0f * 0.25f * g_scal[0] / g_scal[1];
}

// ---------------- launch ----------------
extern "C" void kernel_launch(void* const* d_in, const int* in_sizes, int n_in,
                              void* d_out, int out_size)
{
    (void)in_sizes; (void)n_in; (void)out_size;
    const float* z          = (const float*)d_in[0];
    const float* mask       = (const float*)d_in[1];
    const float* cb         = (const float*)d_in[2];
    const float* ema_count  = (const float*)d_in[3];
    const float* ema_weight = (const float*)d_in[4];

    float* out        = (float*)d_out;
    float* out_q      = out;
    float* out_idx    = out_q + (size_t)NROWS * D;
    float* out_loss   = out_idx + NROWS;
    float* out_count  = out_loss + 1;
    float* out_weight = out_count + KCODES;

    static bool attr_set = false;
    if (!attr_set) {
        cudaFuncSetAttribute(vq_mma_kernel,
                             cudaFuncAttributeMaxDynamicSharedMemorySize, SMEM_TOTAL);
        attr_set = true;
    }

    vq_init_kernel<<<(KCODES * D) / 256, 256>>>(ema_weight, out_weight);
    vq_cnorm_kernel<<<KCODES, 256>>>(cb);
    vq_pack_kernel<<<(NROWS * KV) / 256, 256>>>(z, 0);
    vq_pack_kernel<<<(KCODES * KV) / 256, 256>>>(cb, 1);
    vq_mma_kernel<<<NROWS / BM, THREADS, SMEM_TOTAL>>>();
    vq_gather_kernel<<<NROWS / 4, 256>>>(z, cb, mask, out_q, out_idx, out_weight);
    vq_finalize_kernel<<<1, 1024>>>(ema_count, out_count, out_loss);
}

// round 5
// speedup vs baseline: 1.8029x; 1.8029x over previous
#include <cuda_runtime.h>
#include <cuda_fp16.h>
#include <stdint.h>

// Problem constants
#define D      256
#define KCODES 4096
#define NROWS  16384

#define THREADS 512
#define BM 128
#define BN 256
#define STAGES_PER_TILE 24        // 3 terms x 8 chunks of k32
#define NT (KCODES / BN)          // 16
#define TOTAL_STAGES (STAGES_PER_TILE * NT)  // 384

// smem stage geometry: rows of 32 halves = 64B, no padding (conflict-free by phase)
#define A_STAGE_BYTES (BM * 64)   // 8192
#define B_STAGE_BYTES (BN * 64)   // 16384
#define STAGE_BYTES   (A_STAGE_BYTES + B_STAGE_BYTES)
#define SMEM_TOTAL    (2 * STAGE_BYTES)   // 49152

#define EMA_DECAY 0.99f
#define ONE_MINUS_DECAY 0.01f
#define EPS 1e-5f

// ---------------- device scratch ----------------
__device__ float g_cnorm[KCODES];
__device__ float g_n[KCODES];
__device__ int   g_idx[NROWS];
__device__ float g_scal[2];
// packed [hi(256) | lo(256)] halves per row, k-permuted within each 32-half chunk
__device__ __half2 g_za[(size_t)NROWS * 256];
__device__ __half2 g_cbp[(size_t)KCODES * 256];

// ---------------- helpers ----------------
__device__ __forceinline__ uint32_t smem_u32(const void* p) {
    uint32_t a;
    asm("{ .reg .u64 t; cvta.to.shared.u64 t, %1; cvt.u32.u64 %0, t; }" : "=r"(a) : "l"(p));
    return a;
}
__device__ __forceinline__ void cpasync16(uint32_t dst, const void* src) {
    asm volatile("cp.async.cg.shared.global [%0], [%1], 16;" :: "r"(dst), "l"(src));
}
__device__ __forceinline__ void cp_commit() {
    asm volatile("cp.async.commit_group;" ::: "memory");
}
__device__ __forceinline__ void cp_wait1() {
    asm volatile("cp.async.wait_group 1;" ::: "memory");
}
__device__ __forceinline__ void cp_wait0() {
    asm volatile("cp.async.wait_group 0;" ::: "memory");
}
__device__ __forceinline__ void mma_f16(float* c, uint32_t a0, uint32_t a1,
                                        uint32_t a2, uint32_t a3,
                                        uint32_t b0, uint32_t b1) {
    asm volatile(
        "mma.sync.aligned.m16n8k16.row.col.f32.f16.f16.f32 "
        "{%0,%1,%2,%3}, {%4,%5,%6,%7}, {%8,%9}, {%0,%1,%2,%3};"
        : "+f"(c[0]), "+f"(c[1]), "+f"(c[2]), "+f"(c[3])
        : "r"(a0), "r"(a1), "r"(a2), "r"(a3), "r"(b0), "r"(b1));
}

// ---------------- kernel 0: init ----------------
__global__ __launch_bounds__(256) void vq_init_kernel(
    const float* __restrict__ ema_weight, float* __restrict__ out_weight)
{
    int i = blockIdx.x * 256 + threadIdx.x;
    out_weight[i] = EMA_DECAY * ema_weight[i];
    if (i < KCODES) g_n[i] = 0.0f;
    if (i < 2) g_scal[i] = 0.0f;
}

// ---------------- kernel 1: codebook half-norms ----------------
__global__ __launch_bounds__(256) void vq_cnorm_kernel(const float* __restrict__ cb)
{
    int k = blockIdx.x;
    float v = cb[(size_t)k * D + threadIdx.x];
    float s = v * v;
    #pragma unroll
    for (int off = 16; off > 0; off >>= 1)
        s += __shfl_down_sync(0xffffffffu, s, off);
    __shared__ float ws[8];
    int lane = threadIdx.x & 31, wid = threadIdx.x >> 5;
    if (lane == 0) ws[wid] = s;
    __syncthreads();
    if (threadIdx.x == 0) {
        float t = 0.f;
        #pragma unroll
        for (int w = 0; w < 8; ++w) t += ws[w];
        g_cnorm[k] = 0.5f * t;
    }
}

// ---------------- kernel 2: fp16 hi/lo split + k-permuted pack ----------------
// output word w (half2): row = w>>8; wi = w&255; section = wi>>7 (0=hi,1=lo);
// ws = wi&127; chunk = ws>>4; p0 = (ws&15)*2; q=p0>>3; j=p0&7;
// kl = 2q + ((j>>1)<<3) + (j&1); d = chunk*32 + kl  (d and d+1 are this word's dims)
__global__ __launch_bounds__(256) void vq_pack_kernel(const float* __restrict__ src, int isB)
{
    int w   = blockIdx.x * 256 + threadIdx.x;
    int row = w >> 8;
    int wi  = w & 255;
    int section = wi >> 7;
    int ws  = wi & 127;
    int chunk = ws >> 4;
    int p0  = (ws & 15) * 2;
    int q   = p0 >> 3, j = p0 & 7;
    int kl  = 2 * q + ((j >> 1) << 3) + (j & 1);
    int d   = chunk * 32 + kl;

    float x0 = src[(size_t)row * D + d];
    float x1 = src[(size_t)row * D + d + 1];
    __half h0 = __float2half_rn(x0);
    __half h1 = __float2half_rn(x1);
    if (section) {
        h0 = __float2half_rn(x0 - __half2float(h0));
        h1 = __float2half_rn(x1 - __half2float(h1));
    }
    __half2 out = __halves2half2(h0, h1);
    if (isB) g_cbp[w] = out;
    else     g_za[w]  = out;
}

// ---------------- kernel 3: fp16-split warp-mma GEMM + fused argmax ----------------
__global__ __launch_bounds__(THREADS, 1) void vq_mma_kernel()
{
    extern __shared__ char smem[];
    const uint32_t sbase = smem_u32(smem);
    const int tid  = threadIdx.x;
    const int wid  = tid >> 5;
    const int lane = tid & 31;
    const int r    = lane >> 2;        // groupID 0..7
    const int q    = lane & 3;         // threadID-in-group
    const int wm   = (wid >> 2) * 32;  // warp row base
    const int wn   = (wid & 3) * 64;   // warp col base
    const int mBase = blockIdx.x * BM;

    // fragment smem byte offsets (one v4 delivers a full k32 for one row)
    uint32_t aoff[2][2];
    #pragma unroll
    for (int mf = 0; mf < 2; ++mf)
        #pragma unroll
        for (int rr = 0; rr < 2; ++rr)
            aoff[mf][rr] = (uint32_t)(wm + mf * 16 + rr * 8 + r) * 64u + (uint32_t)q * 16u;
    uint32_t boff[8];
    #pragma unroll
    for (int nf = 0; nf < 8; ++nf)
        boff[nf] = (uint32_t)(wn + nf * 8 + r) * 64u + (uint32_t)q * 16u;

    float acc[2][8][4];
    float bestS[2][2];
    int   bestI[2][2];
    #pragma unroll
    for (int mf = 0; mf < 2; ++mf)
        #pragma unroll
        for (int rr = 0; rr < 2; ++rr) { bestS[mf][rr] = -3.402823e38f; bestI[mf][rr] = 0x7fffffff; }

    // ---- cp.async stage issue (half2-word addressing) ----
    auto issue = [&](int s, int buf) {
        int nt = s / STAGES_PER_TILE;
        int st = s - nt * STAGES_PER_TILE;
        int term = st >> 3;
        int kc   = st & 7;
        // word offsets: row stride 256, lo-section +128, chunk kc*16
        const __half2* Asrc = g_za  + (size_t)mBase * 256
                              + (term < 2 ? 0 : 128) + kc * 16;
        const __half2* Bsrc = g_cbp + (size_t)(nt * BN) * 256
                              + (term == 1 ? 128 : 0) + kc * 16;
        uint32_t abase = sbase + (uint32_t)buf * STAGE_BYTES;
        uint32_t bbase = abase + A_STAGE_BYTES;
        {
            int i = tid;                       // 512 chunks for A
            int row = i >> 2, c = i & 3;
            cpasync16(abase + (uint32_t)row * 64u + (uint32_t)c * 16u,
                      Asrc + (size_t)row * 256 + c * 4);
        }
        #pragma unroll
        for (int t = 0; t < 2; ++t) {          // 1024 chunks for B
            int i = tid + t * THREADS;
            int row = i >> 2, c = i & 3;
            cpasync16(bbase + (uint32_t)row * 64u + (uint32_t)c * 16u,
                      Bsrc + (size_t)row * 256 + c * 4);
        }
        cp_commit();
    };

    issue(0, 0);

    for (int s = 0; s < TOTAL_STAGES; ++s) {
        const int buf = s & 1;
        if (s < TOTAL_STAGES - 1) { issue(s + 1, buf ^ 1); cp_wait1(); }
        else                       { cp_wait0(); }
        __syncthreads();

        int nt = s / STAGES_PER_TILE;
        int ks = s - nt * STAGES_PER_TILE;
        if (ks == 0) {
            #pragma unroll
            for (int mf = 0; mf < 2; ++mf)
                #pragma unroll
                for (int nf = 0; nf < 8; ++nf)
                    #pragma unroll
                    for (int e = 0; e < 4; ++e) acc[mf][nf][e] = 0.0f;
        }

        uint32_t abase = sbase + (uint32_t)buf * STAGE_BYTES;
        uint32_t bbase = abase + A_STAGE_BYTES;

        uint4 Af[2][2];
        #pragma unroll
        for (int mf = 0; mf < 2; ++mf)
            #pragma unroll
            for (int rr = 0; rr < 2; ++rr) {
                uint32_t addr = abase + aoff[mf][rr];
                asm volatile("ld.shared.v4.b32 {%0,%1,%2,%3}, [%4];"
                    : "=r"(Af[mf][rr].x), "=r"(Af[mf][rr].y),
                      "=r"(Af[mf][rr].z), "=r"(Af[mf][rr].w)
                    : "r"(addr));
            }
        #pragma unroll
        for (int nf = 0; nf < 8; ++nf) {
            uint4 Bf;
            uint32_t addr = bbase + boff[nf];
            asm volatile("ld.shared.v4.b32 {%0,%1,%2,%3}, [%4];"
                : "=r"(Bf.x), "=r"(Bf.y), "=r"(Bf.z), "=r"(Bf.w)
                : "r"(addr));
            #pragma unroll
            for (int mf = 0; mf < 2; ++mf) {
                // k16 step 0 (k 0..15 of this k32)
                mma_f16(acc[mf][nf],
                        Af[mf][0].x, Af[mf][1].x, Af[mf][0].y, Af[mf][1].y,
                        Bf.x, Bf.y);
                // k16 step 1 (k 16..31)
                mma_f16(acc[mf][nf],
                        Af[mf][0].z, Af[mf][1].z, Af[mf][0].w, Af[mf][1].w,
                        Bf.z, Bf.w);
            }
        }

        if (ks == STAGES_PER_TILE - 1) {
            int ntBase = nt * BN;
            #pragma unroll
            for (int nf = 0; nf < 8; ++nf) {
                int colb = ntBase + wn + nf * 8 + q * 2;
                float cn0 = __ldg(&g_cnorm[colb]);
                float cn1 = __ldg(&g_cnorm[colb + 1]);
                #pragma unroll
                for (int mf = 0; mf < 2; ++mf) {
                    float s0 = acc[mf][nf][0] - cn0;
                    float s1 = acc[mf][nf][1] - cn1;
                    float s2 = acc[mf][nf][2] - cn0;
                    float s3 = acc[mf][nf][3] - cn1;
                    if (s0 > bestS[mf][0]) { bestS[mf][0] = s0; bestI[mf][0] = colb; }
                    if (s1 > bestS[mf][0]) { bestS[mf][0] = s1; bestI[mf][0] = colb + 1; }
                    if (s2 > bestS[mf][1]) { bestS[mf][1] = s2; bestI[mf][1] = colb; }
                    if (s3 > bestS[mf][1]) { bestS[mf][1] = s3; bestI[mf][1] = colb + 1; }
                }
            }
        }
        __syncthreads();
    }

    // ---- final cross-thread reduction (16 candidates per row) ----
    float* redS = reinterpret_cast<float*>(smem);
    int*   redI = reinterpret_cast<int*>(smem + BM * 16 * 4);
    int c16 = (wid & 3) * 4 + q;
    #pragma unroll
    for (int mf = 0; mf < 2; ++mf)
        #pragma unroll
        for (int rr = 0; rr < 2; ++rr) {
            int row = wm + mf * 16 + rr * 8 + r;
            redS[row * 16 + c16] = bestS[mf][rr];
            redI[row * 16 + c16] = bestI[mf][rr];
        }
    __syncthreads();
    if (tid < BM) {
        float bs = redS[tid * 16];
        int   bi = redI[tid * 16];
        #pragma unroll
        for (int j = 1; j < 16; ++j) {
            float sv = redS[tid * 16 + j];
            int   iv = redI[tid * 16 + j];
            if (sv > bs || (sv == bs && iv < bi)) { bs = sv; bi = iv; }
        }
        g_idx[mBase + tid] = bi;
    }
}

// ---------------- kernel 4: gather + loss + EMA scatter ----------------
__global__ __launch_bounds__(256) void vq_gather_kernel(
    const float* __restrict__ z, const float* __restrict__ cb,
    const float* __restrict__ mask,
    float* __restrict__ out_q, float* __restrict__ out_idx,
    float* __restrict__ out_weight)
{
    int tid = threadIdx.x;
    int l   = tid & 63;
    int row = blockIdx.x * 4 + (tid >> 6);
    int idx = g_idx[row];
    float m = mask[row];

    float4 zv = reinterpret_cast<const float4*>(z  + (size_t)row * D)[l];
    float4 qv = reinterpret_cast<const float4*>(cb + (size_t)idx * D)[l];
    float4 o;
    o.x = zv.x + (qv.x - zv.x); o.y = zv.y + (qv.y - zv.y);
    o.z = zv.z + (qv.z - zv.z); o.w = zv.w + (qv.w - zv.w);
    reinterpret_cast<float4*>(out_q + (size_t)row * D)[l] = o;

    if (m != 0.0f) {
        float* w = out_weight + (size_t)idx * D + l * 4;
        atomicAdd(w + 0, ONE_MINUS_DECAY * m * zv.x);
        atomicAdd(w + 1, ONE_MINUS_DECAY * m * zv.y);
        atomicAdd(w + 2, ONE_MINUS_DECAY * m * zv.z);
        atomicAdd(w + 3, ONE_MINUS_DECAY * m * zv.w);
    }

    float dx = zv.x - qv.x, dy = zv.y - qv.y, dz = zv.z - qv.z, dw = zv.w - qv.w;
    float s = m * (dx * dx + dy * dy + dz * dz + dw * dw);
    #pragma unroll
    for (int off = 16; off > 0; off >>= 1)
        s += __shfl_down_sync(0xffffffffu, s, off);
    __shared__ float ws[8];
    int lane = tid & 31, wd = tid >> 5;
    if (lane == 0) ws[wd] = s;
    __syncthreads();
    if (tid == 0) {
        float t = 0.f;
        #pragma unroll
        for (int w = 0; w < 8; ++w) t += ws[w];
        atomicAdd(&g_scal[0], t * (1.0f / (float)D));
    }
    if (l == 0) {
        out_idx[row] = (float)idx;
        atomicAdd(&g_scal[1], m);
        atomicAdd(&g_n[idx], m);
    }
}

// ---------------- kernel 5: finalize ----------------
__global__ __launch_bounds__(1024) void vq_finalize_kernel(
    const float* __restrict__ ema_count,
    float* __restrict__ out_count, float* __restrict__ out_loss)
{
    __shared__ float cbuf[KCODES];
    __shared__ float red[32];
    __shared__ float s_total;
    int tid = threadIdx.x;

    float local = 0.0f;
    for (int k = tid; k < KCODES; k += 1024) {
        float c = EMA_DECAY * ema_count[k] + ONE_MINUS_DECAY * g_n[k];
        cbuf[k] = c;
        local += c;
    }
    #pragma unroll
    for (int off = 16; off > 0; off >>= 1)
        local += __shfl_down_sync(0xffffffffu, local, off);
    int lane = tid & 31, wid = tid >> 5;
    if (lane == 0) red[wid] = local;
    __syncthreads();
    if (wid == 0) {
        float v = red[lane];
        #pragma unroll
        for (int off = 16; off > 0; off >>= 1)
            v += __shfl_down_sync(0xffffffffu, v, off);
        if (lane == 0) s_total = v;
    }
    __syncthreads();
    float total = s_total;
    float inv = total / (total + (float)KCODES * EPS);
    for (int k = tid; k < KCODES; k += 1024)
        out_count[k] = (cbuf[k] + EPS) * inv;

    if (tid == 0)
        out_loss[0] = 10.0f * 0.25f * g_scal[0] / g_scal[1];
}

// ---------------- launch ----------------
extern "C" void kernel_launch(void* const* d_in, const int* in_sizes, int n_in,
                              void* d_out, int out_size)
{
    (void)in_sizes; (void)n_in; (void)out_size;
    const float* z          = (const float*)d_in[0];
    const float* mask       = (const float*)d_in[1];
    const float* cb         = (const float*)d_in[2];
    const float* ema_count  = (const float*)d_in[3];
    const float* ema_weight = (const float*)d_in[4];

    float* out        = (float*)d_out;
    float* out_q      = out;
    float* out_idx    = out_q + (size_t)NROWS * D;
    float* out_loss   = out_idx + NROWS;
    float* out_count  = out_loss + 1;
    float* out_weight = out_count + KCODES;

    static bool attr_set = false;
    if (!attr_set) {
        cudaFuncSetAttribute(vq_mma_kernel,
                             cudaFuncAttributeMaxDynamicSharedMemorySize, SMEM_TOTAL);
        attr_set = true;
    }

    vq_init_kernel<<<(KCODES * D) / 256, 256>>>(ema_weight, out_weight);
    vq_cnorm_kernel<<<KCODES, 256>>>(cb);
    vq_pack_kernel<<<NROWS, 256>>>(z, 0);          // NROWS*256 half2 words
    vq_pack_kernel<<<KCODES, 256>>>(cb, 1);        // KCODES*256 half2 words
    vq_mma_kernel<<<NROWS / BM, THREADS, SMEM_TOTAL>>>();
    vq_gather_kernel<<<NROWS / 4, 256>>>(z, cb, mask, out_q, out_idx, out_weight);
    vq_finalize_kernel<<<1, 1024>>>(ema_count, out_count, out_loss);
}